// round 3
// baseline (speedup 1.0000x reference)
#include <cuda_runtime.h>
#include <math.h>

// ---------------------------------------------------------------------------
// HyperGraphEncoder — fp32, FFMA2 GEMMs + fused per-step GRU (GEMM+gate)
// ---------------------------------------------------------------------------

typedef unsigned long long ull;

namespace {
constexpr int NB   = 256;
constexpr int HD   = 256;
constexpr int NHEAD = 4;
constexpr int DKH  = 64;
constexpr int TNA  = 127;
constexpr int TNP  = 23;
constexpr int TNH  = 11;
constexpr int G3   = 768;
}

// -------------------------- device scratch ---------------------------------
__device__ float g_atom_f [NB*TNA*HD];
__device__ float g_pharm_f[NB*TNP*HD];
__device__ float g_hyper_f[NB*TNH*HD];
__device__ float g_q1 [NB*TNP*HD];
__device__ float g_k1 [NB*TNH*HD];
__device__ float g_v1 [NB*TNH*HD];
__device__ float g_o1 [NB*TNP*HD];
__device__ float g_pharm2[NB*TNP*HD];
__device__ float g_q2 [NB*TNA*HD];
__device__ float g_k2 [NB*TNP*HD];
__device__ float g_v2 [NB*TNP*HD];
__device__ float g_o2 [NB*TNA*HD];
__device__ float g_h  [NB*TNA*HD];
__device__ float g_gi_f[(size_t)NB*TNA*G3];
__device__ float g_gi_b[(size_t)NB*TNA*G3];
__device__ float g_hcur[2*NB*HD];     // [dir][b][j]
__device__ float g_outsum[2*NB*HD];
__device__ int   g_starts[3*(NB+1)];

// -------------------------- f32x2 helpers -----------------------------------
__device__ __forceinline__ ull pk2(float x) {
    ull r; asm("mov.b64 %0,{%1,%1};" : "=l"(r) : "f"(x)); return r;
}
__device__ __forceinline__ void fma2(ull& d, ull a, ull b) {
    asm("fma.rn.f32x2 %0,%1,%2,%0;" : "+l"(d) : "l"(a), "l"(b));
}
__device__ __forceinline__ void unpk2(ull v, float& lo, float& hi) {
    asm("mov.b64 {%0,%1},%2;" : "=f"(lo), "=f"(hi) : "l"(v));
}

// -------------------------- prefix sums ------------------------------------
__global__ void prefix_kernel(const int* __restrict__ ac,
                              const int* __restrict__ pc,
                              const int* __restrict__ hc) {
    int w = threadIdx.x;
    if (w < 3) {
        const int* c = (w == 0) ? ac : (w == 1) ? pc : hc;
        int* s = (int*)(g_starts + w * (NB + 1));
        int acc = 0;
        for (int i = 0; i < NB; i++) { s[i] = acc; acc += c[i]; }
        s[NB] = acc;
    }
}

// -------------------------- gather / zero-pad -------------------------------
__global__ void gather_kernel(const float* __restrict__ msg,
                              const int* __restrict__ counts,
                              int which, float* __restrict__ out, int maxN) {
    int j = blockIdx.x, b = blockIdx.y;
    int cnt = counts[b];
    float4* dst = (float4*)(out + ((size_t)b * maxN + j) * HD);
    if (j < cnt) {
        int src_row = g_starts[which * (NB + 1) + b] + j;
        const float4* src = (const float4*)(msg + (size_t)src_row * HD);
        dst[threadIdx.x] = src[threadIdx.x];
    } else {
        dst[threadIdx.x] = make_float4(0.f, 0.f, 0.f, 0.f);
    }
}

// -------------------------- FFMA2 SGEMM (64M x 128N tile, BK=16) -------------
template <bool TRANSB>
__global__ void __launch_bounds__(256)
sgemm2_kernel(const float* __restrict__ A, const float* __restrict__ Bm,
              const float* __restrict__ bias, const float* __restrict__ resid,
              float* __restrict__ C, int M, int N, int K) {
    __shared__ float As[16][64];
    __shared__ float Bs[16][128];
    int m0 = blockIdx.y * 64, n0 = blockIdx.x * 128;
    int tid = threadIdx.x;
    int tx = tid & 15, ty = tid >> 4;
    ull acc[4][4] = {};
    for (int k0 = 0; k0 < K; k0 += 16) {
        {
            int row = tid >> 2, seg = tid & 3;
            float4 a = *(const float4*)&A[(size_t)(m0 + row) * K + k0 + seg * 4];
            As[seg*4+0][row] = a.x; As[seg*4+1][row] = a.y;
            As[seg*4+2][row] = a.z; As[seg*4+3][row] = a.w;
        }
        if (!TRANSB) {
            int row = tid >> 4, cs = tid & 15;
            *(float4*)&Bs[row][cs*8]     = *(const float4*)&Bm[(size_t)(k0 + row) * N + n0 + cs*8];
            *(float4*)&Bs[row][cs*8 + 4] = *(const float4*)&Bm[(size_t)(k0 + row) * N + n0 + cs*8 + 4];
        } else {
            int n = tid >> 1, seg = tid & 1;
            float4 b0 = *(const float4*)&Bm[(size_t)(n0 + n) * K + k0 + seg*8];
            float4 b1 = *(const float4*)&Bm[(size_t)(n0 + n) * K + k0 + seg*8 + 4];
            Bs[seg*8+0][n] = b0.x; Bs[seg*8+1][n] = b0.y;
            Bs[seg*8+2][n] = b0.z; Bs[seg*8+3][n] = b0.w;
            Bs[seg*8+4][n] = b1.x; Bs[seg*8+5][n] = b1.y;
            Bs[seg*8+6][n] = b1.z; Bs[seg*8+7][n] = b1.w;
        }
        __syncthreads();
#pragma unroll
        for (int k = 0; k < 16; k++) {
            float4 av = *(const float4*)&As[k][ty * 4];
            ull a0 = pk2(av.x), a1 = pk2(av.y), a2 = pk2(av.z), a3 = pk2(av.w);
            const ulonglong2* bp = (const ulonglong2*)&Bs[k][tx * 8];
            ulonglong2 b01 = bp[0], b23 = bp[1];
            fma2(acc[0][0], a0, b01.x); fma2(acc[0][1], a0, b01.y);
            fma2(acc[0][2], a0, b23.x); fma2(acc[0][3], a0, b23.y);
            fma2(acc[1][0], a1, b01.x); fma2(acc[1][1], a1, b01.y);
            fma2(acc[1][2], a1, b23.x); fma2(acc[1][3], a1, b23.y);
            fma2(acc[2][0], a2, b01.x); fma2(acc[2][1], a2, b01.y);
            fma2(acc[2][2], a2, b23.x); fma2(acc[2][3], a2, b23.y);
            fma2(acc[3][0], a3, b01.x); fma2(acc[3][1], a3, b01.y);
            fma2(acc[3][2], a3, b23.x); fma2(acc[3][3], a3, b23.y);
        }
        __syncthreads();
    }
#pragma unroll
    for (int i = 0; i < 4; i++) {
        int m = m0 + ty * 4 + i;
#pragma unroll
        for (int p = 0; p < 4; p++) {
            int n = n0 + tx * 8 + p * 2;
            float lo, hi;
            unpk2(acc[i][p], lo, hi);
            if (bias)  { lo += bias[n]; hi += bias[n + 1]; }
            if (resid) { float2 rv = *(const float2*)&resid[(size_t)m * N + n];
                         lo += rv.x; hi += rv.y; }
            float2 o; o.x = lo; o.y = hi;
            *(float2*)&C[(size_t)m * N + n] = o;
        }
    }
}

// -------------------------- attention ---------------------------------------
template <int LQ, int LK>
__global__ void attn_kernel(const float* __restrict__ qh,
                            const float* __restrict__ kh,
                            const float* __restrict__ vh,
                            const int* __restrict__ qc,
                            const int* __restrict__ kc,
                            float* __restrict__ o) {
    __shared__ float ks[LK * DKH];
    __shared__ float vs[LK * DKH];
    int bh = blockIdx.x;
    int b = bh / NHEAD, hd = bh % NHEAD;
    for (int idx = threadIdx.x; idx < LK * DKH; idx += blockDim.x) {
        int k = idx / DKH, i = idx % DKH;
        size_t base = ((size_t)(b * LK) + k) * HD + hd * DKH + i;
        ks[idx] = kh[base];
        vs[idx] = vh[base];
    }
    __syncthreads();
    int q = threadIdx.x;
    if (q >= LQ) return;

    float qreg[DKH];
    const float* qp = &qh[((size_t)(b * LQ) + q) * HD + hd * DKH];
#pragma unroll
    for (int i = 0; i < DKH; i++) qreg[i] = qp[i];

    bool vq = q < qc[b];
    int kcnt = kc[b];
    float s[LK];
    float mx = -3.402823e38f;
#pragma unroll
    for (int k = 0; k < LK; k++) {
        float d = 0.f;
#pragma unroll
        for (int i = 0; i < DKH; i++) d = fmaf(qreg[i], ks[k * DKH + i], d);
        float val = (vq && k < kcnt) ? d * 0.125f : -1e9f;
        s[k] = val;
        mx = fmaxf(mx, val);
    }
    float sum = 0.f;
#pragma unroll
    for (int k = 0; k < LK; k++) { s[k] = expf(s[k] - mx); sum += s[k]; }
    float inv = 1.f / sum;
    float* op = &o[((size_t)(b * LQ) + q) * HD + hd * DKH];
#pragma unroll
    for (int i = 0; i < DKH; i++) {
        float a = 0.f;
#pragma unroll
        for (int k = 0; k < LK; k++) a = fmaf(s[k], vs[k * DKH + i], a);
        op[i] = a * inv;
    }
}

// -------------------------- h0 = max over t ---------------------------------
__global__ void hmax_kernel() {
    int b = blockIdx.x, j = threadIdx.x;
    float m = -3.402823e38f;
    for (int t = 0; t < TNA; t++)
        m = fmaxf(m, g_h[((size_t)(b * TNA) + t) * HD + j]);
    g_hcur[(size_t)b * HD + j] = m;
    g_hcur[(size_t)NB * HD + (size_t)b * HD + j] = m;
}

__global__ void zero_outsum_kernel() {
    int idx = blockIdx.x * blockDim.x + threadIdx.x;
    g_outsum[idx] = 0.f;
}

// -------------------------- fused GRU step (GEMM + gate) ---------------------
// grid (4 jt, 16 mt, 2 dir), 256 threads.
// Block computes gh for 16 batches x 64 cols x {r,z,n} (192 N-cols of Whh^T),
// then applies the gate locally: writes hcur, accumulates outsum.
__global__ void __launch_bounds__(256)
gru_step_kernel(const float* __restrict__ Whh_f, const float* __restrict__ Whh_b,
                const float* __restrict__ bhh_f, const float* __restrict__ bhh_b,
                const int* __restrict__ counts, int t) {
    __shared__ float As[16][16];
    __shared__ float Bs[16][192];
    int jt = blockIdx.x, mt = blockIdx.y, gd = blockIdx.z;
    int tid = threadIdx.x;
    int tx = tid & 15, ty = tid >> 4;
    const float* Whh = gd ? Whh_b : Whh_f;
    const float* hcur = g_hcur + (size_t)gd * NB * HD;

    ull acc[3][2] = {};   // gate g, pair of f32x2 covering 4 cols
    for (int k0 = 0; k0 < HD; k0 += 16) {
        {   // A: 16 batches x 16 k — thread (kk = tid&15, bb = tid>>4)
            int kk = tid & 15, bb = tid >> 4;
            As[kk][bb] = hcur[(size_t)(mt * 16 + bb) * HD + k0 + kk];
        }
        {   // B: 192 rows x 16 k; idx = tid + l*256; kseg = idx/192, row = idx%192
#pragma unroll
            for (int l = 0; l < 3; l++) {
                int idx = tid + l * 256;
                int kseg = idx / 192, row = idx - kseg * 192;
                int nrow = jt * 64 + (row & 63) + (row >> 6) * 256;
                float4 bv = *(const float4*)&Whh[(size_t)nrow * HD + k0 + kseg * 4];
                Bs[kseg*4+0][row] = bv.x; Bs[kseg*4+1][row] = bv.y;
                Bs[kseg*4+2][row] = bv.z; Bs[kseg*4+3][row] = bv.w;
            }
        }
        __syncthreads();
#pragma unroll
        for (int k = 0; k < 16; k++) {
            ull a = pk2(As[k][ty]);
#pragma unroll
            for (int g = 0; g < 3; g++) {
                ulonglong2 bv = *(const ulonglong2*)&Bs[k][g * 64 + tx * 4];
                fma2(acc[g][0], a, bv.x);
                fma2(acc[g][1], a, bv.y);
            }
        }
        __syncthreads();
    }

    // ---- gate for batch b = mt*16+ty, cols j = jt*64 + tx*4 .. +3 ----
    int b = mt * 16 + ty;
    int j = jt * 64 + tx * 4;
    int teff = gd ? (TNA - 1 - t) : t;
    const float* gi = (gd ? g_gi_b : g_gi_f) + ((size_t)b * TNA + teff) * G3 + j;
    const float* bhh = gd ? bhh_b : bhh_f;

    float gh[3][4];
#pragma unroll
    for (int g = 0; g < 3; g++) {
        unpk2(acc[g][0], gh[g][0], gh[g][1]);
        unpk2(acc[g][1], gh[g][2], gh[g][3]);
    }
    float4 gir = *(const float4*)&gi[0];
    float4 giz = *(const float4*)&gi[256];
    float4 gin = *(const float4*)&gi[512];
    float4 bhr = *(const float4*)&bhh[j];
    float4 bhz = *(const float4*)&bhh[j + 256];
    float4 bhn = *(const float4*)&bhh[j + 512];

    size_t hidx = (size_t)gd * NB * HD + (size_t)b * HD + j;
    float4 hp = *(float4*)&g_hcur[hidx];

    float irv[4] = {gir.x, gir.y, gir.z, gir.w};
    float izv[4] = {giz.x, giz.y, giz.z, giz.w};
    float inv_[4] = {gin.x, gin.y, gin.z, gin.w};
    float brv[4] = {bhr.x, bhr.y, bhr.z, bhr.w};
    float bzv[4] = {bhz.x, bhz.y, bhz.z, bhz.w};
    float bnv[4] = {bhn.x, bhn.y, bhn.z, bhn.w};
    float hpv[4] = {hp.x, hp.y, hp.z, hp.w};
    float hv[4];
#pragma unroll
    for (int c = 0; c < 4; c++) {
        float r = 1.f / (1.f + expf(-(irv[c] + gh[0][c] + brv[c])));
        float z = 1.f / (1.f + expf(-(izv[c] + gh[1][c] + bzv[c])));
        float n = tanhf(inv_[c] + r * (gh[2][c] + bnv[c]));
        hv[c] = (1.f - z) * n + z * hpv[c];
    }
    float4 ho; ho.x = hv[0]; ho.y = hv[1]; ho.z = hv[2]; ho.w = hv[3];
    *(float4*)&g_hcur[hidx] = ho;

    if (teff < counts[b]) {
        float4 os = *(float4*)&g_outsum[hidx];
        os.x += hv[0]; os.y += hv[1]; os.z += hv[2]; os.w += hv[3];
        *(float4*)&g_outsum[hidx] = os;
    }
}

__global__ void final_kernel(const int* __restrict__ counts, float* __restrict__ out) {
    int idx = blockIdx.x * blockDim.x + threadIdx.x;
    int d = idx >> 16;
    int b = (idx >> 8) & 255;
    int j = idx & 255;
    float c = (float)counts[b];
    out[(size_t)b * 512 + d * 256 + j] =
        g_outsum[(size_t)d * NB * HD + (size_t)b * HD + j] / c;
}

// -------------------------- host launch -------------------------------------
static float* symaddr(const void* sym) {
    void* p = nullptr;
    cudaGetSymbolAddress(&p, sym);
    return (float*)p;
}

extern "C" void kernel_launch(void* const* d_in, const int* in_sizes, int n_in,
                              void* d_out, int out_size) {
    int wbase, ci0, ci1, ci2;
    if (in_sizes[3] == NB) { ci0 = 3; ci1 = 4; ci2 = 5; wbase = 6; }
    else { wbase = 3; ci0 = n_in - 3; ci1 = n_in - 2; ci2 = n_in - 1; }

    const float* atom_msg  = (const float*)d_in[0];
    const float* pharm_msg = (const float*)d_in[1];
    const float* hyper_msg = (const float*)d_in[2];
    const int* ac = (const int*)d_in[ci0];
    const int* pc = (const int*)d_in[ci1];
    const int* hc = (const int*)d_in[ci2];

    const float* p2h[8];
    const float* a2p[8];
    for (int i = 0; i < 8; i++) p2h[i] = (const float*)d_in[wbase + i];
    for (int i = 0; i < 8; i++) a2p[i] = (const float*)d_in[wbase + 8 + i];
    const float* Wih_f = (const float*)d_in[wbase + 16];
    const float* Whh_f = (const float*)d_in[wbase + 17];
    const float* bih_f = (const float*)d_in[wbase + 18];
    const float* bhh_f = (const float*)d_in[wbase + 19];
    const float* Wih_b = (const float*)d_in[wbase + 20];
    const float* Whh_b = (const float*)d_in[wbase + 21];
    const float* bih_b = (const float*)d_in[wbase + 22];
    const float* bhh_b = (const float*)d_in[wbase + 23];

    float* atom_f  = symaddr(g_atom_f);
    float* pharm_f = symaddr(g_pharm_f);
    float* hyper_f = symaddr(g_hyper_f);
    float* q1 = symaddr(g_q1);
    float* k1 = symaddr(g_k1);
    float* v1 = symaddr(g_v1);
    float* o1 = symaddr(g_o1);
    float* pharm2 = symaddr(g_pharm2);
    float* q2 = symaddr(g_q2);
    float* k2 = symaddr(g_k2);
    float* v2 = symaddr(g_v2);
    float* o2 = symaddr(g_o2);
    float* hbuf = symaddr(g_h);
    float* gi_f = symaddr(g_gi_f);
    float* gi_b = symaddr(g_gi_b);

    float* out = (float*)d_out;

    const int MA = NB * TNA;   // 32512
    const int MP = NB * TNP;   // 5888
    const int MH = NB * TNH;   // 2816

    prefix_kernel<<<1, 32>>>(ac, pc, hc);

    gather_kernel<<<dim3(TNA, NB), 64>>>(atom_msg,  ac, 0, atom_f,  TNA);
    gather_kernel<<<dim3(TNP, NB), 64>>>(pharm_msg, pc, 1, pharm_f, TNP);
    gather_kernel<<<dim3(TNH, NB), 64>>>(hyper_msg, hc, 2, hyper_f, TNH);

    // MHA1 (pharm queries, hyper kv)
    sgemm2_kernel<false><<<dim3(HD/128, MP/64), 256>>>(pharm_f, p2h[0], p2h[1], nullptr, q1, MP, HD, HD);
    sgemm2_kernel<false><<<dim3(HD/128, MH/64), 256>>>(hyper_f, p2h[2], p2h[3], nullptr, k1, MH, HD, HD);
    sgemm2_kernel<false><<<dim3(HD/128, MH/64), 256>>>(hyper_f, p2h[4], p2h[5], nullptr, v1, MH, HD, HD);
    attn_kernel<TNP, TNH><<<NB * NHEAD, 32>>>(q1, k1, v1, pc, hc, o1);
    sgemm2_kernel<false><<<dim3(HD/128, MP/64), 256>>>(o1, p2h[6], p2h[7], pharm_f, pharm2, MP, HD, HD);

    // MHA2 (atom queries, updated-pharm kv)
    sgemm2_kernel<false><<<dim3(HD/128, MA/64), 256>>>(atom_f, a2p[0], a2p[1], nullptr, q2, MA, HD, HD);
    sgemm2_kernel<false><<<dim3(HD/128, MP/64), 256>>>(pharm2, a2p[2], a2p[3], nullptr, k2, MP, HD, HD);
    sgemm2_kernel<false><<<dim3(HD/128, MP/64), 256>>>(pharm2, a2p[4], a2p[5], nullptr, v2, MP, HD, HD);
    attn_kernel<TNA, TNP><<<NB * NHEAD, 128>>>(q2, k2, v2, ac, pc, o2);
    sgemm2_kernel<false><<<dim3(HD/128, MA/64), 256>>>(o2, a2p[6], a2p[7], atom_f, hbuf, MA, HD, HD);

    // h0 = max over t (both GRU directions)
    hmax_kernel<<<NB, HD>>>();

    // GRU input precompute gi = h @ Wih^T + bih (per direction)
    sgemm2_kernel<true><<<dim3(G3/128, MA/64), 256>>>(hbuf, Wih_f, bih_f, nullptr, gi_f, MA, G3, HD);
    sgemm2_kernel<true><<<dim3(G3/128, MA/64), 256>>>(hbuf, Wih_b, bih_b, nullptr, gi_b, MA, G3, HD);

    // GRU recurrence: one fused kernel per step
    zero_outsum_kernel<<<(2 * NB * HD) / 256, 256>>>();
    for (int t = 0; t < TNA; t++) {
        gru_step_kernel<<<dim3(4, 16, 2), 256>>>(Whh_f, Whh_b, bhh_f, bhh_b, ac, t);
    }

    final_kernel<<<(2 * NB * HD) / 256, 256>>>(ac, out);
    (void)out_size; (void)n_in;
}